// round 8
// baseline (speedup 1.0000x reference)
#include <cuda_runtime.h>
#include <cuda_bf16.h>
#include <cstdint>

// ---------------------------------------------------------------------------
// Problem constants
// ---------------------------------------------------------------------------
#define MTOK   8192          // B_*S tokens
#define D      4096
#define NADAPT 8
#define RANK   16
#define NR     128           // NADAPT*RANK
#define KTOT   4224          // D + NR, concatenated GEMM K
#define LSCALE 2.0f          // ALPHA/RANK
#define KS     4             // K-split factor for gemm_h

// ---------------------------------------------------------------------------
// Global scratch (static __device__ arrays: allocation-guard-safe)
// ---------------------------------------------------------------------------
__device__ __align__(128) float          g_Hp[KS * MTOK * NR];
__device__ __align__(128) __nv_bfloat16  g_Xh[(size_t)MTOK * KTOT];
__device__ __align__(128) __nv_bfloat16  g_Xl[(size_t)MTOK * KTOT];
__device__ __align__(128) __nv_bfloat16  g_Bh[(size_t)D    * KTOT];
__device__ __align__(128) __nv_bfloat16  g_Bl[(size_t)D    * KTOT];

// ---------------------------------------------------------------------------
// Helpers
// ---------------------------------------------------------------------------
__device__ __forceinline__ void cp_async16(void* smem, const void* gmem) {
    uint32_t sa = (uint32_t)__cvta_generic_to_shared(smem);
    asm volatile("cp.async.cg.shared.global [%0], [%1], 16;\n" :: "r"(sa), "l"(gmem));
}
__device__ __forceinline__ void cp_commit() { asm volatile("cp.async.commit_group;\n"); }
__device__ __forceinline__ void cp_wait0()  { asm volatile("cp.async.wait_group 0;\n"); }

// bf16 split of two fp32 values: hi = truncate-to-bf16 (exact residual), lo = rn-bf16.
__device__ __forceinline__ void split2(float f0, float f1, uint32_t& hi, uint32_t& lo) {
    uint32_t u0 = __float_as_uint(f0), u1 = __float_as_uint(f1);
    asm("prmt.b32 %0, %1, %2, 0x7632;" : "=r"(hi) : "r"(u0), "r"(u1));
    float h0 = __uint_as_float(u0 & 0xffff0000u);
    float h1 = __uint_as_float(u1 & 0xffff0000u);
    float l0 = f0 - h0;
    float l1 = f1 - h1;
    asm("cvt.rn.bf16x2.f32 %0, %1, %2;" : "=r"(lo) : "f"(l1), "f"(l0));
}

__device__ __forceinline__ void mma_bf16(float c[4],
                                         uint32_t a0, uint32_t a1, uint32_t a2, uint32_t a3,
                                         uint32_t b0, uint32_t b1) {
    asm volatile(
        "mma.sync.aligned.m16n8k16.row.col.f32.bf16.bf16.f32 "
        "{%0,%1,%2,%3}, {%4,%5,%6,%7}, {%8,%9}, {%0,%1,%2,%3};\n"
        : "+f"(c[0]), "+f"(c[1]), "+f"(c[2]), "+f"(c[3])
        : "r"(a0), "r"(a1), "r"(a2), "r"(a3), "r"(b0), "r"(b1));
}

// ---------------------------------------------------------------------------
// Kernel 1: H partial = (x @ A_all^T) * coef over a 1024-wide K slice
// grid (KS, 64), 256 threads (unchanged from R6 — ~90us)
// ---------------------------------------------------------------------------
#define BM 128
#define BN 128
#define BK 16
#define SROW 24

__global__ __launch_bounds__(256)
void gemm_h(const float* __restrict__ X, const float* __restrict__ loraA,
            const float* __restrict__ lw) {
    __shared__ float Xs[2][BM * SROW];
    __shared__ float Ws[2][BN * SROW];

    const int tid = threadIdx.x;
    const int m0  = blockIdx.y * BM;
    const int ksp = blockIdx.x;
    const int wid = tid >> 5, lane = tid & 31;
    const int wm  = wid >> 2, wn = wid & 3;
    const int g   = lane >> 2, tig = lane & 3;

    float acc[4][4][4];
#pragma unroll
    for (int mt = 0; mt < 4; mt++)
#pragma unroll
        for (int nt = 0; nt < 4; nt++)
#pragma unroll
            for (int i = 0; i < 4; i++) acc[mt][nt][i] = 0.0f;

    const int lr = tid >> 2;
    const int lc = (tid & 3) * 4;

    auto issue = [&](int kt, int buf) {
        const float* ga = X + (size_t)m0 * D + kt * BK;
        const float* gb = loraA + kt * BK;
#pragma unroll
        for (int p = 0; p < 2; p++) {
            int r = p * 64 + lr;
            cp_async16(&Xs[buf][r * SROW + lc], ga + (size_t)r * D + lc);
            cp_async16(&Ws[buf][r * SROW + lc], gb + (size_t)r * D + lc);
        }
        cp_commit();
    };

    const int kt0 = ksp * (D / BK / KS);
    const int kt1 = kt0 + (D / BK / KS);

    issue(kt0, 0);
    cp_wait0();
    __syncthreads();

    for (int kt = kt0; kt < kt1; kt++) {
        const int cur = kt & 1;
        if (kt + 1 < kt1) issue(kt + 1, cur ^ 1);

        const float* Xc = Xs[cur];
        const float* Wc = Ws[cur];
        uint32_t bh[4][2], bl[4][2];
#pragma unroll
        for (int nt = 0; nt < 4; nt++) {
            const float* bb = &Wc[(wn * 32 + nt * 8 + g) * SROW + 2 * tig];
            float2 v0 = *(const float2*)bb;
            float2 v1 = *(const float2*)(bb + 8);
            split2(v0.x, v0.y, bh[nt][0], bl[nt][0]);
            split2(v1.x, v1.y, bh[nt][1], bl[nt][1]);
        }
#pragma unroll
        for (int mt = 0; mt < 4; mt++) {
            const float* ar = &Xc[(wm * 64 + mt * 16 + g) * SROW + 2 * tig];
            float2 u0 = *(const float2*)ar;
            float2 u1 = *(const float2*)(ar + 8 * SROW);
            float2 u2 = *(const float2*)(ar + 8);
            float2 u3 = *(const float2*)(ar + 8 * SROW + 8);
            uint32_t ah[4], al[4];
            split2(u0.x, u0.y, ah[0], al[0]);
            split2(u1.x, u1.y, ah[1], al[1]);
            split2(u2.x, u2.y, ah[2], al[2]);
            split2(u3.x, u3.y, ah[3], al[3]);
#pragma unroll
            for (int nt = 0; nt < 4; nt++) {
                mma_bf16(acc[mt][nt], ah[0], ah[1], ah[2], ah[3], bh[nt][0], bh[nt][1]);
                mma_bf16(acc[mt][nt], al[0], al[1], al[2], al[3], bh[nt][0], bh[nt][1]);
                mma_bf16(acc[mt][nt], ah[0], ah[1], ah[2], ah[3], bl[nt][0], bl[nt][1]);
            }
        }
        cp_wait0();
        __syncthreads();
    }

    float* Hp = g_Hp + (size_t)ksp * MTOK * NR;
#pragma unroll
    for (int mt = 0; mt < 4; mt++) {
        const int row = m0 + wm * 64 + mt * 16 + g;
#pragma unroll
        for (int nt = 0; nt < 4; nt++) {
            const int col = wn * 32 + nt * 8 + 2 * tig;
            const float c = LSCALE * __ldg(&lw[col >> 4]);
            float2 v0 = make_float2(acc[mt][nt][0] * c, acc[mt][nt][1] * c);
            float2 v1 = make_float2(acc[mt][nt][2] * c, acc[mt][nt][3] * c);
            *(float2*)&Hp[(size_t)row * NR + col]       = v0;
            *(float2*)&Hp[(size_t)(row + 8) * NR + col] = v1;
        }
    }
}

// ---------------------------------------------------------------------------
// Kernel 2: convert [x | sum(Hp)] -> g_Xh / g_Xl
// ---------------------------------------------------------------------------
__global__ __launch_bounds__(256)
void convert_x(const float* __restrict__ x) {
    size_t idx = (size_t)blockIdx.x * 256 + threadIdx.x;
    size_t e   = idx * 4;
    int m = (int)(e / KTOT);
    int k = (int)(e % KTOT);
    float4 v;
    if (k < D) {
        v = *(const float4*)&x[(size_t)m * D + k];
    } else {
        size_t off = (size_t)m * NR + (k - D);
        float4 p0 = *(const float4*)&g_Hp[off];
        float4 p1 = *(const float4*)&g_Hp[(size_t)1 * MTOK * NR + off];
        float4 p2 = *(const float4*)&g_Hp[(size_t)2 * MTOK * NR + off];
        float4 p3 = *(const float4*)&g_Hp[(size_t)3 * MTOK * NR + off];
        v.x = (p0.x + p1.x) + (p2.x + p3.x);
        v.y = (p0.y + p1.y) + (p2.y + p3.y);
        v.z = (p0.z + p1.z) + (p2.z + p3.z);
        v.w = (p0.w + p1.w) + (p2.w + p3.w);
    }
    uint32_t h0, l0, h1, l1;
    split2(v.x, v.y, h0, l0);
    split2(v.z, v.w, h1, l1);
    *(uint2*)&g_Xh[(size_t)m * KTOT + k] = make_uint2(h0, h1);
    *(uint2*)&g_Xl[(size_t)m * KTOT + k] = make_uint2(l0, l1);
}

// ---------------------------------------------------------------------------
// Kernel 3: convert [W | B_all] -> g_Bh / g_Bl
// ---------------------------------------------------------------------------
__global__ __launch_bounds__(256)
void convert_b(const float* __restrict__ W, const float* __restrict__ loraB) {
    size_t idx = (size_t)blockIdx.x * 256 + threadIdx.x;
    size_t e   = idx * 4;
    int n = (int)(e / KTOT);
    int k = (int)(e % KTOT);
    float4 v;
    if (k < D) {
        v = *(const float4*)&W[(size_t)n * D + k];
    } else {
        int na = (k - D) >> 4;
        int r  = (k - D) & 15;
        v = *(const float4*)&loraB[((size_t)na * D + n) * RANK + r];
    }
    uint32_t h0, l0, h1, l1;
    split2(v.x, v.y, h0, l0);
    split2(v.z, v.w, h1, l1);
    *(uint2*)&g_Bh[(size_t)n * KTOT + k] = make_uint2(h0, h1);
    *(uint2*)&g_Bl[(size_t)n * KTOT + k] = make_uint2(l0, l1);
}

// ---------------------------------------------------------------------------
// Kernel 4: main GEMM on precomputed bf16 planes.
//   CTA tile 256(m) x 128(n) x BKB=32; 512 threads = 16 warps in 4(m) x 4(n);
//   warp tile 64x32 -> 4x4 m16n8k16 tiles, 2 ksteps, 3 passes = 96 HMMA/warp/iter.
//   smem per stage: Ah/Al 256xSRB + Bh/Bl 128xSRB bf16 = 61440 B; x2 = 120 KB.
//   1 CTA/SM; barrier overhead amortized over ~4x more MMA work than R6.
// ---------------------------------------------------------------------------
#define TMM   256
#define TNN   128
#define BKB   32
#define SRB   40
#define APL   (TMM * SRB)                 // 10240 bf16
#define BPL   (TNN * SRB)                 // 5120 bf16
#define STG   (2 * APL + 2 * BPL)         // 30720 bf16 per stage
#define SMEM_MAIN (2 * STG * 2)           // 122880 bytes

__global__ __launch_bounds__(512)
void gemm_mainp(const float* __restrict__ bias, float* __restrict__ out) {
    extern __shared__ __align__(16) __nv_bfloat16 sm[];

    const int tid = threadIdx.x;
    const int m0  = blockIdx.y * TMM;
    const int n0  = blockIdx.x * TNN;
    const int wid = tid >> 5, lane = tid & 31;
    const int wm  = wid >> 2, wn = wid & 3;      // 4x4 warp grid
    const int g   = lane >> 2, tig = lane & 3;

    float acc[4][4][4];
#pragma unroll
    for (int mt = 0; mt < 4; mt++)
#pragma unroll
        for (int nt = 0; nt < 4; nt++)
#pragma unroll
            for (int i = 0; i < 4; i++) acc[mt][nt][i] = 0.0f;

    const int lr  = tid >> 2;          // 0..127
    const int lch = (tid & 3) * 8;     // bf16 offset 0,8,16,24 (16B chunks)

    const __nv_bfloat16* gXh = g_Xh + (size_t)m0 * KTOT;
    const __nv_bfloat16* gXl = g_Xl + (size_t)m0 * KTOT;
    const __nv_bfloat16* gBh = g_Bh + (size_t)n0 * KTOT;
    const __nv_bfloat16* gBl = g_Bl + (size_t)n0 * KTOT;

    auto issue = [&](int kt, int buf) {
        const size_t gk = (size_t)kt * BKB;
        __nv_bfloat16* s = sm + buf * STG;
        // A planes: 256 rows, two passes of 128
#pragma unroll
        for (int p = 0; p < 2; p++) {
            const int r = p * 128 + lr;
            const size_t go = (size_t)r * KTOT + gk + lch;
            const int so = r * SRB + lch;
            cp_async16(&s[so],        gXh + go);
            cp_async16(&s[APL + so],  gXl + go);
        }
        // B planes: 128 rows, one pass
        {
            const size_t go = (size_t)lr * KTOT + gk + lch;
            const int so = lr * SRB + lch;
            cp_async16(&s[2 * APL + so],       gBh + go);
            cp_async16(&s[2 * APL + BPL + so], gBl + go);
        }
        cp_commit();
    };

    issue(0, 0);
    cp_wait0();
    __syncthreads();

    const int NKT = KTOT / BKB;   // 132
    for (int kt = 0; kt < NKT; kt++) {
        const int cur = kt & 1;
        if (kt + 1 < NKT) issue(kt + 1, cur ^ 1);

        const __nv_bfloat16* s = sm + cur * STG;
#pragma unroll
        for (int ks = 0; ks < 2; ks++) {
            const int kk = ks * 16;
            uint32_t bh[4][2], bl[4][2];
#pragma unroll
            for (int nt = 0; nt < 4; nt++) {
                const int base = (wn * 32 + nt * 8 + g) * SRB + kk + 2 * tig;
                bh[nt][0] = *(const uint32_t*)&s[2 * APL + base];
                bh[nt][1] = *(const uint32_t*)&s[2 * APL + base + 8];
                bl[nt][0] = *(const uint32_t*)&s[2 * APL + BPL + base];
                bl[nt][1] = *(const uint32_t*)&s[2 * APL + BPL + base + 8];
            }
#pragma unroll
            for (int mt = 0; mt < 4; mt++) {
                const int ab = (wm * 64 + mt * 16 + g) * SRB + kk + 2 * tig;
                uint32_t ah0 = *(const uint32_t*)&s[ab];
                uint32_t ah1 = *(const uint32_t*)&s[ab + 8 * SRB];
                uint32_t ah2 = *(const uint32_t*)&s[ab + 8];
                uint32_t ah3 = *(const uint32_t*)&s[ab + 8 * SRB + 8];
                uint32_t al0 = *(const uint32_t*)&s[APL + ab];
                uint32_t al1 = *(const uint32_t*)&s[APL + ab + 8 * SRB];
                uint32_t al2 = *(const uint32_t*)&s[APL + ab + 8];
                uint32_t al3 = *(const uint32_t*)&s[APL + ab + 8 * SRB + 8];
#pragma unroll
                for (int nt = 0; nt < 4; nt++) {
                    mma_bf16(acc[mt][nt], ah0, ah1, ah2, ah3, bh[nt][0], bh[nt][1]);
                    mma_bf16(acc[mt][nt], al0, al1, al2, al3, bh[nt][0], bh[nt][1]);
                    mma_bf16(acc[mt][nt], ah0, ah1, ah2, ah3, bl[nt][0], bl[nt][1]);
                }
            }
        }
        cp_wait0();
        __syncthreads();
    }

    // Epilogue: add bias, write out
#pragma unroll
    for (int mt = 0; mt < 4; mt++) {
        const int row = m0 + wm * 64 + mt * 16 + g;
#pragma unroll
        for (int nt = 0; nt < 4; nt++) {
            const int col = n0 + wn * 32 + nt * 8 + 2 * tig;
            const float b0 = __ldg(&bias[col]);
            const float b1 = __ldg(&bias[col + 1]);
            float2 v0 = make_float2(acc[mt][nt][0] + b0, acc[mt][nt][1] + b1);
            float2 v1 = make_float2(acc[mt][nt][2] + b0, acc[mt][nt][3] + b1);
            *(float2*)&out[(size_t)row * D + col]       = v0;
            *(float2*)&out[(size_t)(row + 8) * D + col] = v1;
        }
    }
}

// ---------------------------------------------------------------------------
// Launch
// ---------------------------------------------------------------------------
extern "C" void kernel_launch(void* const* d_in, const int* in_sizes, int n_in,
                              void* d_out, int out_size) {
    const float* x     = (const float*)d_in[0];   // [4,2048,4096]
    const float* loraA = (const float*)d_in[1];   // [8,16,4096]
    const float* loraB = (const float*)d_in[2];   // [8,4096,16]
    const float* W     = (const float*)d_in[3];   // [4096,4096]
    const float* bias  = (const float*)d_in[4];   // [4096]
    const float* lw    = (const float*)d_in[5];   // [8]
    float* out = (float*)d_out;

    static bool attr_set = false;
    if (!attr_set) {
        cudaFuncSetAttribute(gemm_mainp, cudaFuncAttributeMaxDynamicSharedMemorySize,
                             SMEM_MAIN);
        attr_set = true;
    }

    gemm_h   <<<dim3(KS, MTOK / BM), 256>>>(x, loraA, lw);
    convert_x<<<(int)((size_t)MTOK * KTOT / 4 / 256), 256>>>(x);
    convert_b<<<(int)((size_t)D * KTOT / 4 / 256), 256>>>(W, loraB);
    gemm_mainp<<<dim3(D / TNN, MTOK / TMM), 512, SMEM_MAIN>>>(bias, out);
}

// round 9
// speedup vs baseline: 1.1520x; 1.1520x over previous
#include <cuda_runtime.h>
#include <cuda_bf16.h>
#include <cstdint>

// ---------------------------------------------------------------------------
// Problem constants
// ---------------------------------------------------------------------------
#define MTOK   8192          // B_*S tokens
#define D      4096
#define NADAPT 8
#define RANK   16
#define NR     128           // NADAPT*RANK
#define KTOT   4224          // D + NR, concatenated GEMM K
#define LSCALE 2.0f          // ALPHA/RANK
#define KS     4             // K-split factor for gemm_h

// ---------------------------------------------------------------------------
// Global scratch (static __device__ arrays: allocation-guard-safe)
// ---------------------------------------------------------------------------
__device__ __align__(128) float          g_Hp[KS * MTOK * NR];
__device__ __align__(128) __nv_bfloat16  g_Xh[(size_t)MTOK * KTOT];
__device__ __align__(128) __nv_bfloat16  g_Xl[(size_t)MTOK * KTOT];
__device__ __align__(128) __nv_bfloat16  g_Bh[(size_t)D    * KTOT];
__device__ __align__(128) __nv_bfloat16  g_Bl[(size_t)D    * KTOT];

// ---------------------------------------------------------------------------
// Helpers
// ---------------------------------------------------------------------------
__device__ __forceinline__ void cp_async16(void* smem, const void* gmem) {
    uint32_t sa = (uint32_t)__cvta_generic_to_shared(smem);
    asm volatile("cp.async.cg.shared.global [%0], [%1], 16;\n" :: "r"(sa), "l"(gmem));
}
__device__ __forceinline__ void cp_commit() { asm volatile("cp.async.commit_group;\n"); }
__device__ __forceinline__ void cp_wait0()  { asm volatile("cp.async.wait_group 0;\n"); }

// bf16 split of two fp32 values: hi = truncate-to-bf16 (exact residual), lo = rn-bf16.
__device__ __forceinline__ void split2(float f0, float f1, uint32_t& hi, uint32_t& lo) {
    uint32_t u0 = __float_as_uint(f0), u1 = __float_as_uint(f1);
    asm("prmt.b32 %0, %1, %2, 0x7632;" : "=r"(hi) : "r"(u0), "r"(u1));
    float h0 = __uint_as_float(u0 & 0xffff0000u);
    float h1 = __uint_as_float(u1 & 0xffff0000u);
    float l0 = f0 - h0;
    float l1 = f1 - h1;
    asm("cvt.rn.bf16x2.f32 %0, %1, %2;" : "=r"(lo) : "f"(l1), "f"(l0));
}

__device__ __forceinline__ void mma_bf16(float c[4],
                                         uint32_t a0, uint32_t a1, uint32_t a2, uint32_t a3,
                                         uint32_t b0, uint32_t b1) {
    asm volatile(
        "mma.sync.aligned.m16n8k16.row.col.f32.bf16.bf16.f32 "
        "{%0,%1,%2,%3}, {%4,%5,%6,%7}, {%8,%9}, {%0,%1,%2,%3};\n"
        : "+f"(c[0]), "+f"(c[1]), "+f"(c[2]), "+f"(c[3])
        : "r"(a0), "r"(a1), "r"(a2), "r"(a3), "r"(b0), "r"(b1));
}

// ---------------------------------------------------------------------------
// Kernel 1: H partial = (x @ A_all^T) * coef over a 1024-wide K slice
// grid (KS, 64), 256 threads
// ---------------------------------------------------------------------------
#define BM 128
#define BN 128
#define BK 16
#define SROW 24

__global__ __launch_bounds__(256)
void gemm_h(const float* __restrict__ X, const float* __restrict__ loraA,
            const float* __restrict__ lw) {
    __shared__ float Xs[2][BM * SROW];
    __shared__ float Ws[2][BN * SROW];

    const int tid = threadIdx.x;
    const int m0  = blockIdx.y * BM;
    const int ksp = blockIdx.x;
    const int wid = tid >> 5, lane = tid & 31;
    const int wm  = wid >> 2, wn = wid & 3;
    const int g   = lane >> 2, tig = lane & 3;

    float acc[4][4][4];
#pragma unroll
    for (int mt = 0; mt < 4; mt++)
#pragma unroll
        for (int nt = 0; nt < 4; nt++)
#pragma unroll
            for (int i = 0; i < 4; i++) acc[mt][nt][i] = 0.0f;

    const int lr = tid >> 2;
    const int lc = (tid & 3) * 4;

    auto issue = [&](int kt, int buf) {
        const float* ga = X + (size_t)m0 * D + kt * BK;
        const float* gb = loraA + kt * BK;
#pragma unroll
        for (int p = 0; p < 2; p++) {
            int r = p * 64 + lr;
            cp_async16(&Xs[buf][r * SROW + lc], ga + (size_t)r * D + lc);
            cp_async16(&Ws[buf][r * SROW + lc], gb + (size_t)r * D + lc);
        }
        cp_commit();
    };

    const int kt0 = ksp * (D / BK / KS);
    const int kt1 = kt0 + (D / BK / KS);

    issue(kt0, 0);
    cp_wait0();
    __syncthreads();

    for (int kt = kt0; kt < kt1; kt++) {
        const int cur = kt & 1;
        if (kt + 1 < kt1) issue(kt + 1, cur ^ 1);

        const float* Xc = Xs[cur];
        const float* Wc = Ws[cur];
        uint32_t bh[4][2], bl[4][2];
#pragma unroll
        for (int nt = 0; nt < 4; nt++) {
            const float* bb = &Wc[(wn * 32 + nt * 8 + g) * SROW + 2 * tig];
            float2 v0 = *(const float2*)bb;
            float2 v1 = *(const float2*)(bb + 8);
            split2(v0.x, v0.y, bh[nt][0], bl[nt][0]);
            split2(v1.x, v1.y, bh[nt][1], bl[nt][1]);
        }
#pragma unroll
        for (int mt = 0; mt < 4; mt++) {
            const float* ar = &Xc[(wm * 64 + mt * 16 + g) * SROW + 2 * tig];
            float2 u0 = *(const float2*)ar;
            float2 u1 = *(const float2*)(ar + 8 * SROW);
            float2 u2 = *(const float2*)(ar + 8);
            float2 u3 = *(const float2*)(ar + 8 * SROW + 8);
            uint32_t ah[4], al[4];
            split2(u0.x, u0.y, ah[0], al[0]);
            split2(u1.x, u1.y, ah[1], al[1]);
            split2(u2.x, u2.y, ah[2], al[2]);
            split2(u3.x, u3.y, ah[3], al[3]);
            // pass-major: same-acc HMMAs are 4 apart (not back-to-back)
#pragma unroll
            for (int nt = 0; nt < 4; nt++)
                mma_bf16(acc[mt][nt], ah[0], ah[1], ah[2], ah[3], bh[nt][0], bh[nt][1]);
#pragma unroll
            for (int nt = 0; nt < 4; nt++)
                mma_bf16(acc[mt][nt], al[0], al[1], al[2], al[3], bh[nt][0], bh[nt][1]);
#pragma unroll
            for (int nt = 0; nt < 4; nt++)
                mma_bf16(acc[mt][nt], ah[0], ah[1], ah[2], ah[3], bl[nt][0], bl[nt][1]);
        }
        cp_wait0();
        __syncthreads();
    }

    float* Hp = g_Hp + (size_t)ksp * MTOK * NR;
#pragma unroll
    for (int mt = 0; mt < 4; mt++) {
        const int row = m0 + wm * 64 + mt * 16 + g;
#pragma unroll
        for (int nt = 0; nt < 4; nt++) {
            const int col = wn * 32 + nt * 8 + 2 * tig;
            const float c = LSCALE * __ldg(&lw[col >> 4]);
            float2 v0 = make_float2(acc[mt][nt][0] * c, acc[mt][nt][1] * c);
            float2 v1 = make_float2(acc[mt][nt][2] * c, acc[mt][nt][3] * c);
            *(float2*)&Hp[(size_t)row * NR + col]       = v0;
            *(float2*)&Hp[(size_t)(row + 8) * NR + col] = v1;
        }
    }
}

// ---------------------------------------------------------------------------
// Kernel 2: convert [x | sum(Hp)] -> g_Xh / g_Xl
// ---------------------------------------------------------------------------
__global__ __launch_bounds__(256)
void convert_x(const float* __restrict__ x) {
    size_t idx = (size_t)blockIdx.x * 256 + threadIdx.x;
    size_t e   = idx * 4;
    int m = (int)(e / KTOT);
    int k = (int)(e % KTOT);
    float4 v;
    if (k < D) {
        v = *(const float4*)&x[(size_t)m * D + k];
    } else {
        size_t off = (size_t)m * NR + (k - D);
        float4 p0 = *(const float4*)&g_Hp[off];
        float4 p1 = *(const float4*)&g_Hp[(size_t)1 * MTOK * NR + off];
        float4 p2 = *(const float4*)&g_Hp[(size_t)2 * MTOK * NR + off];
        float4 p3 = *(const float4*)&g_Hp[(size_t)3 * MTOK * NR + off];
        v.x = (p0.x + p1.x) + (p2.x + p3.x);
        v.y = (p0.y + p1.y) + (p2.y + p3.y);
        v.z = (p0.z + p1.z) + (p2.z + p3.z);
        v.w = (p0.w + p1.w) + (p2.w + p3.w);
    }
    uint32_t h0, l0, h1, l1;
    split2(v.x, v.y, h0, l0);
    split2(v.z, v.w, h1, l1);
    *(uint2*)&g_Xh[(size_t)m * KTOT + k] = make_uint2(h0, h1);
    *(uint2*)&g_Xl[(size_t)m * KTOT + k] = make_uint2(l0, l1);
}

// ---------------------------------------------------------------------------
// Kernel 3: convert [W | B_all] -> g_Bh / g_Bl
// ---------------------------------------------------------------------------
__global__ __launch_bounds__(256)
void convert_b(const float* __restrict__ W, const float* __restrict__ loraB) {
    size_t idx = (size_t)blockIdx.x * 256 + threadIdx.x;
    size_t e   = idx * 4;
    int n = (int)(e / KTOT);
    int k = (int)(e % KTOT);
    float4 v;
    if (k < D) {
        v = *(const float4*)&W[(size_t)n * D + k];
    } else {
        int na = (k - D) >> 4;
        int r  = (k - D) & 15;
        v = *(const float4*)&loraB[((size_t)na * D + n) * RANK + r];
    }
    uint32_t h0, l0, h1, l1;
    split2(v.x, v.y, h0, l0);
    split2(v.z, v.w, h1, l1);
    *(uint2*)&g_Bh[(size_t)n * KTOT + k] = make_uint2(h0, h1);
    *(uint2*)&g_Bl[(size_t)n * KTOT + k] = make_uint2(l0, l1);
}

// ---------------------------------------------------------------------------
// Kernel 4: main GEMM on precomputed bf16 planes (R6 memory config exactly:
//   128x128 x BKB=32 tile, 256 thr, 2-stage cp.async double buffer, SRB=40,
//   2 CTAs/SM). Change vs R6: pass-major mma order so same-accumulator HMMAs
//   are 4 apart, breaking the acc RAW chain that idled the tensor pipe.
// ---------------------------------------------------------------------------
#define BKB   32
#define SRB   40
#define PLANE (128 * SRB)                  // bf16 units per plane tile
#define SMEM_MAIN (2 * 4 * PLANE * 2)      // bytes = 81920

__global__ __launch_bounds__(256)
void gemm_mainp(const float* __restrict__ bias, float* __restrict__ out) {
    extern __shared__ __align__(16) __nv_bfloat16 sm[];

    const int tid = threadIdx.x;
    const int m0  = blockIdx.y * BM;
    const int n0  = blockIdx.x * BN;
    const int wid = tid >> 5, lane = tid & 31;
    const int wm  = wid >> 2, wn = wid & 3;
    const int g   = lane >> 2, tig = lane & 3;

    float acc[4][4][4];
#pragma unroll
    for (int mt = 0; mt < 4; mt++)
#pragma unroll
        for (int nt = 0; nt < 4; nt++)
#pragma unroll
            for (int i = 0; i < 4; i++) acc[mt][nt][i] = 0.0f;

    const int lr  = tid >> 2;          // 0..63 row
    const int lch = (tid & 3) * 8;     // bf16 chunk offset 0,8,16,24

    const __nv_bfloat16* gXh = g_Xh + (size_t)m0 * KTOT;
    const __nv_bfloat16* gXl = g_Xl + (size_t)m0 * KTOT;
    const __nv_bfloat16* gBh = g_Bh + (size_t)n0 * KTOT;
    const __nv_bfloat16* gBl = g_Bl + (size_t)n0 * KTOT;

    auto issue = [&](int kt, int buf) {
        const size_t gk = (size_t)kt * BKB;
        __nv_bfloat16* s = sm + buf * 4 * PLANE;
#pragma unroll
        for (int p = 0; p < 2; p++) {
            const int r = p * 64 + lr;
            const size_t go = (size_t)r * KTOT + gk + lch;
            const int so = r * SRB + lch;
            cp_async16(&s[so],             gXh + go);
            cp_async16(&s[PLANE + so],     gXl + go);
            cp_async16(&s[2 * PLANE + so], gBh + go);
            cp_async16(&s[3 * PLANE + so], gBl + go);
        }
        cp_commit();
    };

    issue(0, 0);
    cp_wait0();
    __syncthreads();

    const int NKT = KTOT / BKB;   // 132
    for (int kt = 0; kt < NKT; kt++) {
        const int cur = kt & 1;
        if (kt + 1 < NKT) issue(kt + 1, cur ^ 1);

        const __nv_bfloat16* s = sm + cur * 4 * PLANE;
#pragma unroll
        for (int ks = 0; ks < 2; ks++) {
            const int kk = ks * 16;
            uint32_t bh[4][2], bl[4][2];
#pragma unroll
            for (int nt = 0; nt < 4; nt++) {
                const int base = (wn * 32 + nt * 8 + g) * SRB + kk + 2 * tig;
                bh[nt][0] = *(const uint32_t*)&s[2 * PLANE + base];
                bh[nt][1] = *(const uint32_t*)&s[2 * PLANE + base + 8];
                bl[nt][0] = *(const uint32_t*)&s[3 * PLANE + base];
                bl[nt][1] = *(const uint32_t*)&s[3 * PLANE + base + 8];
            }
#pragma unroll
            for (int mt = 0; mt < 4; mt++) {
                const int ab = (wm * 64 + mt * 16 + g) * SRB + kk + 2 * tig;
                uint32_t ah0 = *(const uint32_t*)&s[ab];
                uint32_t ah1 = *(const uint32_t*)&s[ab + 8 * SRB];
                uint32_t ah2 = *(const uint32_t*)&s[ab + 8];
                uint32_t ah3 = *(const uint32_t*)&s[ab + 8 * SRB + 8];
                uint32_t al0 = *(const uint32_t*)&s[PLANE + ab];
                uint32_t al1 = *(const uint32_t*)&s[PLANE + ab + 8 * SRB];
                uint32_t al2 = *(const uint32_t*)&s[PLANE + ab + 8];
                uint32_t al3 = *(const uint32_t*)&s[PLANE + ab + 8 * SRB + 8];
                // pass-major: acc[mt][nt] reused at distance 4, not back-to-back
#pragma unroll
                for (int nt = 0; nt < 4; nt++)
                    mma_bf16(acc[mt][nt], ah0, ah1, ah2, ah3, bh[nt][0], bh[nt][1]);
#pragma unroll
                for (int nt = 0; nt < 4; nt++)
                    mma_bf16(acc[mt][nt], al0, al1, al2, al3, bh[nt][0], bh[nt][1]);
#pragma unroll
                for (int nt = 0; nt < 4; nt++)
                    mma_bf16(acc[mt][nt], ah0, ah1, ah2, ah3, bl[nt][0], bl[nt][1]);
            }
        }
        cp_wait0();
        __syncthreads();
    }

    // Epilogue: add bias, write out
#pragma unroll
    for (int mt = 0; mt < 4; mt++) {
        const int row = m0 + wm * 64 + mt * 16 + g;
#pragma unroll
        for (int nt = 0; nt < 4; nt++) {
            const int col = n0 + wn * 32 + nt * 8 + 2 * tig;
            const float b0 = __ldg(&bias[col]);
            const float b1 = __ldg(&bias[col + 1]);
            float2 v0 = make_float2(acc[mt][nt][0] + b0, acc[mt][nt][1] + b1);
            float2 v1 = make_float2(acc[mt][nt][2] + b0, acc[mt][nt][3] + b1);
            *(float2*)&out[(size_t)row * D + col]       = v0;
            *(float2*)&out[(size_t)(row + 8) * D + col] = v1;
        }
    }
}

// ---------------------------------------------------------------------------
// Launch
// ---------------------------------------------------------------------------
extern "C" void kernel_launch(void* const* d_in, const int* in_sizes, int n_in,
                              void* d_out, int out_size) {
    const float* x     = (const float*)d_in[0];   // [4,2048,4096]
    const float* loraA = (const float*)d_in[1];   // [8,16,4096]
    const float* loraB = (const float*)d_in[2];   // [8,4096,16]
    const float* W     = (const float*)d_in[3];   // [4096,4096]
    const float* bias  = (const float*)d_in[4];   // [4096]
    const float* lw    = (const float*)d_in[5];   // [8]
    float* out = (float*)d_out;

    static bool attr_set = false;
    if (!attr_set) {
        cudaFuncSetAttribute(gemm_mainp, cudaFuncAttributeMaxDynamicSharedMemorySize,
                             SMEM_MAIN);
        attr_set = true;
    }

    gemm_h   <<<dim3(KS, MTOK / BM), 256>>>(x, loraA, lw);
    convert_x<<<(int)((size_t)MTOK * KTOT / 4 / 256), 256>>>(x);
    convert_b<<<(int)((size_t)D * KTOT / 4 / 256), 256>>>(W, loraB);
    gemm_mainp<<<dim3(D / BN, MTOK / BM), 256, SMEM_MAIN>>>(bias, out);
}

// round 10
// speedup vs baseline: 1.1632x; 1.0097x over previous
#include <cuda_runtime.h>
#include <cuda_bf16.h>
#include <cstdint>

// ---------------------------------------------------------------------------
// Problem constants
// ---------------------------------------------------------------------------
#define MTOK   8192          // B_*S tokens
#define D      4096
#define NADAPT 8
#define RANK   16
#define NR     128           // NADAPT*RANK
#define KTOT   4224          // D + NR, concatenated GEMM K
#define LSCALE 2.0f          // ALPHA/RANK
#define KS     4             // K-split factor for gemm_h

// ---------------------------------------------------------------------------
// Global scratch (static __device__ arrays: allocation-guard-safe)
// ---------------------------------------------------------------------------
__device__ __align__(128) float          g_Hp[KS * MTOK * NR];
__device__ __align__(128) __nv_bfloat16  g_Xh[(size_t)MTOK * KTOT];
__device__ __align__(128) __nv_bfloat16  g_Xl[(size_t)MTOK * KTOT];
__device__ __align__(128) __nv_bfloat16  g_Bh[(size_t)D    * KTOT];
__device__ __align__(128) __nv_bfloat16  g_Bl[(size_t)D    * KTOT];

// ---------------------------------------------------------------------------
// Helpers
// ---------------------------------------------------------------------------
__device__ __forceinline__ void cp_async16(void* smem, const void* gmem) {
    uint32_t sa = (uint32_t)__cvta_generic_to_shared(smem);
    asm volatile("cp.async.cg.shared.global [%0], [%1], 16;\n" :: "r"(sa), "l"(gmem));
}
__device__ __forceinline__ void cp_commit() { asm volatile("cp.async.commit_group;\n"); }
__device__ __forceinline__ void cp_wait0()  { asm volatile("cp.async.wait_group 0;\n"); }

// bf16 split of two fp32 values: hi = truncate-to-bf16 (exact residual), lo = rn-bf16.
__device__ __forceinline__ void split2(float f0, float f1, uint32_t& hi, uint32_t& lo) {
    uint32_t u0 = __float_as_uint(f0), u1 = __float_as_uint(f1);
    asm("prmt.b32 %0, %1, %2, 0x7632;" : "=r"(hi) : "r"(u0), "r"(u1));
    float h0 = __uint_as_float(u0 & 0xffff0000u);
    float h1 = __uint_as_float(u1 & 0xffff0000u);
    float l0 = f0 - h0;
    float l1 = f1 - h1;
    asm("cvt.rn.bf16x2.f32 %0, %1, %2;" : "=r"(lo) : "f"(l1), "f"(l0));
}

__device__ __forceinline__ void mma_bf16(float c[4],
                                         uint32_t a0, uint32_t a1, uint32_t a2, uint32_t a3,
                                         uint32_t b0, uint32_t b1) {
    asm volatile(
        "mma.sync.aligned.m16n8k16.row.col.f32.bf16.bf16.f32 "
        "{%0,%1,%2,%3}, {%4,%5,%6,%7}, {%8,%9}, {%0,%1,%2,%3};\n"
        : "+f"(c[0]), "+f"(c[1]), "+f"(c[2]), "+f"(c[3])
        : "r"(a0), "r"(a1), "r"(a2), "r"(a3), "r"(b0), "r"(b1));
}

// ldmatrix x4: loads 4 8x8 b16 tiles; lane l supplies row address of tile l>>3.
__device__ __forceinline__ void ldsm4(uint32_t& r0, uint32_t& r1, uint32_t& r2, uint32_t& r3,
                                      uint32_t addr) {
    asm volatile("ldmatrix.sync.aligned.m8n8.x4.shared.b16 {%0,%1,%2,%3}, [%4];"
                 : "=r"(r0), "=r"(r1), "=r"(r2), "=r"(r3) : "r"(addr));
}

// ---------------------------------------------------------------------------
// Kernel 1: H partial = (x @ A_all^T) * coef over a 1024-wide K slice
// grid (KS, 64), 256 threads (unchanged — ~90us)
// ---------------------------------------------------------------------------
#define BM 128
#define BN 128
#define BK 16
#define SROW 24

__global__ __launch_bounds__(256)
void gemm_h(const float* __restrict__ X, const float* __restrict__ loraA,
            const float* __restrict__ lw) {
    __shared__ float Xs[2][BM * SROW];
    __shared__ float Ws[2][BN * SROW];

    const int tid = threadIdx.x;
    const int m0  = blockIdx.y * BM;
    const int ksp = blockIdx.x;
    const int wid = tid >> 5, lane = tid & 31;
    const int wm  = wid >> 2, wn = wid & 3;
    const int g   = lane >> 2, tig = lane & 3;

    float acc[4][4][4];
#pragma unroll
    for (int mt = 0; mt < 4; mt++)
#pragma unroll
        for (int nt = 0; nt < 4; nt++)
#pragma unroll
            for (int i = 0; i < 4; i++) acc[mt][nt][i] = 0.0f;

    const int lr = tid >> 2;
    const int lc = (tid & 3) * 4;

    auto issue = [&](int kt, int buf) {
        const float* ga = X + (size_t)m0 * D + kt * BK;
        const float* gb = loraA + kt * BK;
#pragma unroll
        for (int p = 0; p < 2; p++) {
            int r = p * 64 + lr;
            cp_async16(&Xs[buf][r * SROW + lc], ga + (size_t)r * D + lc);
            cp_async16(&Ws[buf][r * SROW + lc], gb + (size_t)r * D + lc);
        }
        cp_commit();
    };

    const int kt0 = ksp * (D / BK / KS);
    const int kt1 = kt0 + (D / BK / KS);

    issue(kt0, 0);
    cp_wait0();
    __syncthreads();

    for (int kt = kt0; kt < kt1; kt++) {
        const int cur = kt & 1;
        if (kt + 1 < kt1) issue(kt + 1, cur ^ 1);

        const float* Xc = Xs[cur];
        const float* Wc = Ws[cur];
        uint32_t bh[4][2], bl[4][2];
#pragma unroll
        for (int nt = 0; nt < 4; nt++) {
            const float* bb = &Wc[(wn * 32 + nt * 8 + g) * SROW + 2 * tig];
            float2 v0 = *(const float2*)bb;
            float2 v1 = *(const float2*)(bb + 8);
            split2(v0.x, v0.y, bh[nt][0], bl[nt][0]);
            split2(v1.x, v1.y, bh[nt][1], bl[nt][1]);
        }
#pragma unroll
        for (int mt = 0; mt < 4; mt++) {
            const float* ar = &Xc[(wm * 64 + mt * 16 + g) * SROW + 2 * tig];
            float2 u0 = *(const float2*)ar;
            float2 u1 = *(const float2*)(ar + 8 * SROW);
            float2 u2 = *(const float2*)(ar + 8);
            float2 u3 = *(const float2*)(ar + 8 * SROW + 8);
            uint32_t ah[4], al[4];
            split2(u0.x, u0.y, ah[0], al[0]);
            split2(u1.x, u1.y, ah[1], al[1]);
            split2(u2.x, u2.y, ah[2], al[2]);
            split2(u3.x, u3.y, ah[3], al[3]);
#pragma unroll
            for (int nt = 0; nt < 4; nt++)
                mma_bf16(acc[mt][nt], ah[0], ah[1], ah[2], ah[3], bh[nt][0], bh[nt][1]);
#pragma unroll
            for (int nt = 0; nt < 4; nt++)
                mma_bf16(acc[mt][nt], al[0], al[1], al[2], al[3], bh[nt][0], bh[nt][1]);
#pragma unroll
            for (int nt = 0; nt < 4; nt++)
                mma_bf16(acc[mt][nt], ah[0], ah[1], ah[2], ah[3], bl[nt][0], bl[nt][1]);
        }
        cp_wait0();
        __syncthreads();
    }

    float* Hp = g_Hp + (size_t)ksp * MTOK * NR;
#pragma unroll
    for (int mt = 0; mt < 4; mt++) {
        const int row = m0 + wm * 64 + mt * 16 + g;
#pragma unroll
        for (int nt = 0; nt < 4; nt++) {
            const int col = wn * 32 + nt * 8 + 2 * tig;
            const float c = LSCALE * __ldg(&lw[col >> 4]);
            float2 v0 = make_float2(acc[mt][nt][0] * c, acc[mt][nt][1] * c);
            float2 v1 = make_float2(acc[mt][nt][2] * c, acc[mt][nt][3] * c);
            *(float2*)&Hp[(size_t)row * NR + col]       = v0;
            *(float2*)&Hp[(size_t)(row + 8) * NR + col] = v1;
        }
    }
}

// ---------------------------------------------------------------------------
// Kernel 2: convert [x | sum(Hp)] -> g_Xh / g_Xl
// ---------------------------------------------------------------------------
__global__ __launch_bounds__(256)
void convert_x(const float* __restrict__ x) {
    size_t idx = (size_t)blockIdx.x * 256 + threadIdx.x;
    size_t e   = idx * 4;
    int m = (int)(e / KTOT);
    int k = (int)(e % KTOT);
    float4 v;
    if (k < D) {
        v = *(const float4*)&x[(size_t)m * D + k];
    } else {
        size_t off = (size_t)m * NR + (k - D);
        float4 p0 = *(const float4*)&g_Hp[off];
        float4 p1 = *(const float4*)&g_Hp[(size_t)1 * MTOK * NR + off];
        float4 p2 = *(const float4*)&g_Hp[(size_t)2 * MTOK * NR + off];
        float4 p3 = *(const float4*)&g_Hp[(size_t)3 * MTOK * NR + off];
        v.x = (p0.x + p1.x) + (p2.x + p3.x);
        v.y = (p0.y + p1.y) + (p2.y + p3.y);
        v.z = (p0.z + p1.z) + (p2.z + p3.z);
        v.w = (p0.w + p1.w) + (p2.w + p3.w);
    }
    uint32_t h0, l0, h1, l1;
    split2(v.x, v.y, h0, l0);
    split2(v.z, v.w, h1, l1);
    *(uint2*)&g_Xh[(size_t)m * KTOT + k] = make_uint2(h0, h1);
    *(uint2*)&g_Xl[(size_t)m * KTOT + k] = make_uint2(l0, l1);
}

// ---------------------------------------------------------------------------
// Kernel 3: convert [W | B_all] -> g_Bh / g_Bl
// ---------------------------------------------------------------------------
__global__ __launch_bounds__(256)
void convert_b(const float* __restrict__ W, const float* __restrict__ loraB) {
    size_t idx = (size_t)blockIdx.x * 256 + threadIdx.x;
    size_t e   = idx * 4;
    int n = (int)(e / KTOT);
    int k = (int)(e % KTOT);
    float4 v;
    if (k < D) {
        v = *(const float4*)&W[(size_t)n * D + k];
    } else {
        int na = (k - D) >> 4;
        int r  = (k - D) & 15;
        v = *(const float4*)&loraB[((size_t)na * D + n) * RANK + r];
    }
    uint32_t h0, l0, h1, l1;
    split2(v.x, v.y, h0, l0);
    split2(v.z, v.w, h1, l1);
    *(uint2*)&g_Bh[(size_t)n * KTOT + k] = make_uint2(h0, h1);
    *(uint2*)&g_Bl[(size_t)n * KTOT + k] = make_uint2(l0, l1);
}

// ---------------------------------------------------------------------------
// Kernel 4: main GEMM on precomputed bf16 planes. Memory config identical to
//   R6/R9 (128x128 x BKB=32, 256 thr, 2-stage double buffer, SRB=40, 2 CTA/SM).
//   Change: ALL fragment loads via ldmatrix.x4 (24 LDSM vs 96 LDS per warp/iter).
//   LDSM bank check: 8 rows at word offsets {20r..+3} mod 32 = all 32 banks.
// ---------------------------------------------------------------------------
#define BKB   32
#define SRB   40
#define PLANE (128 * SRB)                  // bf16 units per plane tile
#define SMEM_MAIN (2 * 4 * PLANE * 2)      // bytes = 81920

__global__ __launch_bounds__(256)
void gemm_mainp(const float* __restrict__ bias, float* __restrict__ out) {
    extern __shared__ __align__(16) __nv_bfloat16 sm[];

    const int tid = threadIdx.x;
    const int m0  = blockIdx.y * BM;
    const int n0  = blockIdx.x * BN;
    const int wid = tid >> 5, lane = tid & 31;
    const int wm  = wid >> 2, wn = wid & 3;
    const int g   = lane >> 2, tig = lane & 3;

    float acc[4][4][4];
#pragma unroll
    for (int mt = 0; mt < 4; mt++)
#pragma unroll
        for (int nt = 0; nt < 4; nt++)
#pragma unroll
            for (int i = 0; i < 4; i++) acc[mt][nt][i] = 0.0f;

    const int lr  = tid >> 2;          // 0..63 row
    const int lch = (tid & 3) * 8;     // bf16 chunk offset 0,8,16,24

    const __nv_bfloat16* gXh = g_Xh + (size_t)m0 * KTOT;
    const __nv_bfloat16* gXl = g_Xl + (size_t)m0 * KTOT;
    const __nv_bfloat16* gBh = g_Bh + (size_t)n0 * KTOT;
    const __nv_bfloat16* gBl = g_Bl + (size_t)n0 * KTOT;

    // ldmatrix lane-address components (bytes, relative to plane base):
    //   A tiles: m0=(r0-7,k0-7) m1=(r8-15,k0-7) m2=(r0-7,k8-15) m3=(r8-15,k8-15)
    //   B tiles (per nt-pair): m0=(n0-7,k0-7) m1=(n0-7,k8-15) m2=(n8-15,k0-7) m3=(n8-15,k8-15)
    const uint32_t sbase = (uint32_t)__cvta_generic_to_shared(sm);
    const int l = lane;
    const uint32_t aLane = (uint32_t)(((wm * 64 + (l & 7) + ((l >> 3) & 1) * 8) * SRB
                                       + ((l >> 4) & 1) * 8) * 2);
    const uint32_t bLane = (uint32_t)(((wn * 32 + (l & 7) + ((l >> 4) & 1) * 8) * SRB
                                       + ((l >> 3) & 1) * 8) * 2);

    auto issue = [&](int kt, int buf) {
        const size_t gk = (size_t)kt * BKB;
        __nv_bfloat16* s = sm + buf * 4 * PLANE;
#pragma unroll
        for (int p = 0; p < 2; p++) {
            const int r = p * 64 + lr;
            const size_t go = (size_t)r * KTOT + gk + lch;
            const int so = r * SRB + lch;
            cp_async16(&s[so],             gXh + go);
            cp_async16(&s[PLANE + so],     gXl + go);
            cp_async16(&s[2 * PLANE + so], gBh + go);
            cp_async16(&s[3 * PLANE + so], gBl + go);
        }
        cp_commit();
    };

    issue(0, 0);
    cp_wait0();
    __syncthreads();

    const int NKT = KTOT / BKB;   // 132
    for (int kt = 0; kt < NKT; kt++) {
        const int cur = kt & 1;
        if (kt + 1 < NKT) issue(kt + 1, cur ^ 1);

        const uint32_t bufB = sbase + (uint32_t)(cur * 4 * PLANE * 2);
        const uint32_t aHB  = bufB + aLane;                         // Ah plane
        const uint32_t aLB  = aHB + PLANE * 2;                      // Al plane
        const uint32_t bHB  = bufB + (uint32_t)(2 * PLANE * 2) + bLane;  // Bh
        const uint32_t bLB  = bHB + PLANE * 2;                      // Bl

#pragma unroll
        for (int ks = 0; ks < 2; ks++) {
            const uint32_t kkB = (uint32_t)(ks * 16 * 2);           // k offset bytes
            uint32_t bh[4][2], bl[4][2];
            // B: one LDSM.x4 per nt-pair per plane
            ldsm4(bh[0][0], bh[0][1], bh[1][0], bh[1][1], bHB + kkB);
            ldsm4(bh[2][0], bh[2][1], bh[3][0], bh[3][1], bHB + kkB + 16 * SRB * 2);
            ldsm4(bl[0][0], bl[0][1], bl[1][0], bl[1][1], bLB + kkB);
            ldsm4(bl[2][0], bl[2][1], bl[3][0], bl[3][1], bLB + kkB + 16 * SRB * 2);
#pragma unroll
            for (int mt = 0; mt < 4; mt++) {
                const uint32_t mtB = (uint32_t)(mt * 16 * SRB * 2);
                uint32_t ah0, ah1, ah2, ah3, al0, al1, al2, al3;
                ldsm4(ah0, ah1, ah2, ah3, aHB + mtB + kkB);
                ldsm4(al0, al1, al2, al3, aLB + mtB + kkB);
#pragma unroll
                for (int nt = 0; nt < 4; nt++)
                    mma_bf16(acc[mt][nt], ah0, ah1, ah2, ah3, bh[nt][0], bh[nt][1]);
#pragma unroll
                for (int nt = 0; nt < 4; nt++)
                    mma_bf16(acc[mt][nt], al0, al1, al2, al3, bh[nt][0], bh[nt][1]);
#pragma unroll
                for (int nt = 0; nt < 4; nt++)
                    mma_bf16(acc[mt][nt], ah0, ah1, ah2, ah3, bl[nt][0], bl[nt][1]);
            }
        }
        cp_wait0();
        __syncthreads();
    }

    // Epilogue: add bias, write out
#pragma unroll
    for (int mt = 0; mt < 4; mt++) {
        const int row = m0 + wm * 64 + mt * 16 + g;
#pragma unroll
        for (int nt = 0; nt < 4; nt++) {
            const int col = n0 + wn * 32 + nt * 8 + 2 * tig;
            const float b0 = __ldg(&bias[col]);
            const float b1 = __ldg(&bias[col + 1]);
            float2 v0 = make_float2(acc[mt][nt][0] + b0, acc[mt][nt][1] + b1);
            float2 v1 = make_float2(acc[mt][nt][2] + b0, acc[mt][nt][3] + b1);
            *(float2*)&out[(size_t)row * D + col]       = v0;
            *(float2*)&out[(size_t)(row + 8) * D + col] = v1;
        }
    }
}

// ---------------------------------------------------------------------------
// Launch
// ---------------------------------------------------------------------------
extern "C" void kernel_launch(void* const* d_in, const int* in_sizes, int n_in,
                              void* d_out, int out_size) {
    const float* x     = (const float*)d_in[0];   // [4,2048,4096]
    const float* loraA = (const float*)d_in[1];   // [8,16,4096]
    const float* loraB = (const float*)d_in[2];   // [8,4096,16]
    const float* W     = (const float*)d_in[3];   // [4096,4096]
    const float* bias  = (const float*)d_in[4];   // [4096]
    const float* lw    = (const float*)d_in[5];   // [8]
    float* out = (float*)d_out;

    static bool attr_set = false;
    if (!attr_set) {
        cudaFuncSetAttribute(gemm_mainp, cudaFuncAttributeMaxDynamicSharedMemorySize,
                             SMEM_MAIN);
        attr_set = true;
    }

    gemm_h   <<<dim3(KS, MTOK / BM), 256>>>(x, loraA, lw);
    convert_x<<<(int)((size_t)MTOK * KTOT / 4 / 256), 256>>>(x);
    convert_b<<<(int)((size_t)D * KTOT / 4 / 256), 256>>>(W, loraB);
    gemm_mainp<<<dim3(D / BN, MTOK / BM), 256, SMEM_MAIN>>>(bias, out);
}

// round 11
// speedup vs baseline: 1.2197x; 1.0485x over previous
#include <cuda_runtime.h>
#include <cuda_bf16.h>
#include <cstdint>

// ---------------------------------------------------------------------------
// Problem constants
// ---------------------------------------------------------------------------
#define MTOK   8192          // B_*S tokens
#define D      4096
#define NADAPT 8
#define RANK   16
#define NR     128           // NADAPT*RANK
#define KTOT   4224          // D + NR, concatenated GEMM K
#define LSCALE 2.0f          // ALPHA/RANK
#define KS     4             // K-split factor for gemm_h

// ---------------------------------------------------------------------------
// Global scratch (static __device__ arrays: allocation-guard-safe)
// ---------------------------------------------------------------------------
__device__ __align__(128) float          g_Hp[KS * MTOK * NR];
__device__ __align__(128) __nv_bfloat16  g_Xh[(size_t)MTOK * KTOT];
__device__ __align__(128) __nv_bfloat16  g_Xl[(size_t)MTOK * KTOT];
__device__ __align__(128) __nv_bfloat16  g_Bh[(size_t)D    * KTOT];
__device__ __align__(128) __nv_bfloat16  g_Bl[(size_t)D    * KTOT];

// ---------------------------------------------------------------------------
// Helpers
// ---------------------------------------------------------------------------
__device__ __forceinline__ void cp_async16(void* smem, const void* gmem) {
    uint32_t sa = (uint32_t)__cvta_generic_to_shared(smem);
    asm volatile("cp.async.cg.shared.global [%0], [%1], 16;\n" :: "r"(sa), "l"(gmem));
}
__device__ __forceinline__ void cp_async16_s(uint32_t sa, const void* gmem) {
    asm volatile("cp.async.cg.shared.global [%0], [%1], 16;\n" :: "r"(sa), "l"(gmem));
}
__device__ __forceinline__ void cp_commit() { asm volatile("cp.async.commit_group;\n"); }
__device__ __forceinline__ void cp_wait0()  { asm volatile("cp.async.wait_group 0;\n"); }
__device__ __forceinline__ void cp_wait1()  { asm volatile("cp.async.wait_group 1;\n"); }

// bf16 split of two fp32 values: hi = truncate-to-bf16 (exact residual), lo = rn-bf16.
__device__ __forceinline__ void split2(float f0, float f1, uint32_t& hi, uint32_t& lo) {
    uint32_t u0 = __float_as_uint(f0), u1 = __float_as_uint(f1);
    asm("prmt.b32 %0, %1, %2, 0x7632;" : "=r"(hi) : "r"(u0), "r"(u1));
    float h0 = __uint_as_float(u0 & 0xffff0000u);
    float h1 = __uint_as_float(u1 & 0xffff0000u);
    float l0 = f0 - h0;
    float l1 = f1 - h1;
    asm("cvt.rn.bf16x2.f32 %0, %1, %2;" : "=r"(lo) : "f"(l1), "f"(l0));
}

__device__ __forceinline__ void mma_bf16(float c[4],
                                         uint32_t a0, uint32_t a1, uint32_t a2, uint32_t a3,
                                         uint32_t b0, uint32_t b1) {
    asm volatile(
        "mma.sync.aligned.m16n8k16.row.col.f32.bf16.bf16.f32 "
        "{%0,%1,%2,%3}, {%4,%5,%6,%7}, {%8,%9}, {%0,%1,%2,%3};\n"
        : "+f"(c[0]), "+f"(c[1]), "+f"(c[2]), "+f"(c[3])
        : "r"(a0), "r"(a1), "r"(a2), "r"(a3), "r"(b0), "r"(b1));
}

__device__ __forceinline__ void ldsm4(uint32_t& r0, uint32_t& r1, uint32_t& r2, uint32_t& r3,
                                      uint32_t addr) {
    asm volatile("ldmatrix.sync.aligned.m8n8.x4.shared.b16 {%0,%1,%2,%3}, [%4];"
                 : "=r"(r0), "=r"(r1), "=r"(r2), "=r"(r3) : "r"(addr));
}

// ---------------------------------------------------------------------------
// Kernel 1: H partial = (x @ A_all^T) * coef over a 1024-wide K slice
// grid (KS, 64), 256 threads (unchanged)
// ---------------------------------------------------------------------------
#define BM 128
#define BN 128
#define BK 16
#define SROW 24

__global__ __launch_bounds__(256)
void gemm_h(const float* __restrict__ X, const float* __restrict__ loraA,
            const float* __restrict__ lw) {
    __shared__ float Xs[2][BM * SROW];
    __shared__ float Ws[2][BN * SROW];

    const int tid = threadIdx.x;
    const int m0  = blockIdx.y * BM;
    const int ksp = blockIdx.x;
    const int wid = tid >> 5, lane = tid & 31;
    const int wm  = wid >> 2, wn = wid & 3;
    const int g   = lane >> 2, tig = lane & 3;

    float acc[4][4][4];
#pragma unroll
    for (int mt = 0; mt < 4; mt++)
#pragma unroll
        for (int nt = 0; nt < 4; nt++)
#pragma unroll
            for (int i = 0; i < 4; i++) acc[mt][nt][i] = 0.0f;

    const int lr = tid >> 2;
    const int lc = (tid & 3) * 4;

    auto issue = [&](int kt, int buf) {
        const float* ga = X + (size_t)m0 * D + kt * BK;
        const float* gb = loraA + kt * BK;
#pragma unroll
        for (int p = 0; p < 2; p++) {
            int r = p * 64 + lr;
            cp_async16(&Xs[buf][r * SROW + lc], ga + (size_t)r * D + lc);
            cp_async16(&Ws[buf][r * SROW + lc], gb + (size_t)r * D + lc);
        }
        cp_commit();
    };

    const int kt0 = ksp * (D / BK / KS);
    const int kt1 = kt0 + (D / BK / KS);

    issue(kt0, 0);
    cp_wait0();
    __syncthreads();

    for (int kt = kt0; kt < kt1; kt++) {
        const int cur = kt & 1;
        if (kt + 1 < kt1) issue(kt + 1, cur ^ 1);

        const float* Xc = Xs[cur];
        const float* Wc = Ws[cur];
        uint32_t bh[4][2], bl[4][2];
#pragma unroll
        for (int nt = 0; nt < 4; nt++) {
            const float* bb = &Wc[(wn * 32 + nt * 8 + g) * SROW + 2 * tig];
            float2 v0 = *(const float2*)bb;
            float2 v1 = *(const float2*)(bb + 8);
            split2(v0.x, v0.y, bh[nt][0], bl[nt][0]);
            split2(v1.x, v1.y, bh[nt][1], bl[nt][1]);
        }
#pragma unroll
        for (int mt = 0; mt < 4; mt++) {
            const float* ar = &Xc[(wm * 64 + mt * 16 + g) * SROW + 2 * tig];
            float2 u0 = *(const float2*)ar;
            float2 u1 = *(const float2*)(ar + 8 * SROW);
            float2 u2 = *(const float2*)(ar + 8);
            float2 u3 = *(const float2*)(ar + 8 * SROW + 8);
            uint32_t ah[4], al[4];
            split2(u0.x, u0.y, ah[0], al[0]);
            split2(u1.x, u1.y, ah[1], al[1]);
            split2(u2.x, u2.y, ah[2], al[2]);
            split2(u3.x, u3.y, ah[3], al[3]);
#pragma unroll
            for (int nt = 0; nt < 4; nt++)
                mma_bf16(acc[mt][nt], ah[0], ah[1], ah[2], ah[3], bh[nt][0], bh[nt][1]);
#pragma unroll
            for (int nt = 0; nt < 4; nt++)
                mma_bf16(acc[mt][nt], al[0], al[1], al[2], al[3], bh[nt][0], bh[nt][1]);
#pragma unroll
            for (int nt = 0; nt < 4; nt++)
                mma_bf16(acc[mt][nt], ah[0], ah[1], ah[2], ah[3], bl[nt][0], bl[nt][1]);
        }
        cp_wait0();
        __syncthreads();
    }

    float* Hp = g_Hp + (size_t)ksp * MTOK * NR;
#pragma unroll
    for (int mt = 0; mt < 4; mt++) {
        const int row = m0 + wm * 64 + mt * 16 + g;
#pragma unroll
        for (int nt = 0; nt < 4; nt++) {
            const int col = wn * 32 + nt * 8 + 2 * tig;
            const float c = LSCALE * __ldg(&lw[col >> 4]);
            float2 v0 = make_float2(acc[mt][nt][0] * c, acc[mt][nt][1] * c);
            float2 v1 = make_float2(acc[mt][nt][2] * c, acc[mt][nt][3] * c);
            *(float2*)&Hp[(size_t)row * NR + col]       = v0;
            *(float2*)&Hp[(size_t)(row + 8) * NR + col] = v1;
        }
    }
}

// ---------------------------------------------------------------------------
// Kernel 2: convert [x | sum(Hp)] -> g_Xh / g_Xl
// ---------------------------------------------------------------------------
__global__ __launch_bounds__(256)
void convert_x(const float* __restrict__ x) {
    size_t idx = (size_t)blockIdx.x * 256 + threadIdx.x;
    size_t e   = idx * 4;
    int m = (int)(e / KTOT);
    int k = (int)(e % KTOT);
    float4 v;
    if (k < D) {
        v = *(const float4*)&x[(size_t)m * D + k];
    } else {
        size_t off = (size_t)m * NR + (k - D);
        float4 p0 = *(const float4*)&g_Hp[off];
        float4 p1 = *(const float4*)&g_Hp[(size_t)1 * MTOK * NR + off];
        float4 p2 = *(const float4*)&g_Hp[(size_t)2 * MTOK * NR + off];
        float4 p3 = *(const float4*)&g_Hp[(size_t)3 * MTOK * NR + off];
        v.x = (p0.x + p1.x) + (p2.x + p3.x);
        v.y = (p0.y + p1.y) + (p2.y + p3.y);
        v.z = (p0.z + p1.z) + (p2.z + p3.z);
        v.w = (p0.w + p1.w) + (p2.w + p3.w);
    }
    uint32_t h0, l0, h1, l1;
    split2(v.x, v.y, h0, l0);
    split2(v.z, v.w, h1, l1);
    *(uint2*)&g_Xh[(size_t)m * KTOT + k] = make_uint2(h0, h1);
    *(uint2*)&g_Xl[(size_t)m * KTOT + k] = make_uint2(l0, l1);
}

// ---------------------------------------------------------------------------
// Kernel 3: convert [W | B_all] -> g_Bh / g_Bl
// ---------------------------------------------------------------------------
__global__ __launch_bounds__(256)
void convert_b(const float* __restrict__ W, const float* __restrict__ loraB) {
    size_t idx = (size_t)blockIdx.x * 256 + threadIdx.x;
    size_t e   = idx * 4;
    int n = (int)(e / KTOT);
    int k = (int)(e % KTOT);
    float4 v;
    if (k < D) {
        v = *(const float4*)&W[(size_t)n * D + k];
    } else {
        int na = (k - D) >> 4;
        int r  = (k - D) & 15;
        v = *(const float4*)&loraB[((size_t)na * D + n) * RANK + r];
    }
    uint32_t h0, l0, h1, l1;
    split2(v.x, v.y, h0, l0);
    split2(v.z, v.w, h1, l1);
    *(uint2*)&g_Bh[(size_t)n * KTOT + k] = make_uint2(h0, h1);
    *(uint2*)&g_Bl[(size_t)n * KTOT + k] = make_uint2(l0, l1);
}

// ---------------------------------------------------------------------------
// Kernel 4: main GEMM, 3-stage cp.async pipeline + XOR swizzle (no padding).
//   128x128 x BKB=32 tile, 256 thr, 2 CTA/SM.
//   Stage: 4 planes x 128 rows x 64B = 32 KB; 3 stages = 96 KB.
//   Swizzle: 16B chunk c stored at physical chunk c ^ ((row>>1)&3).
//     LDSM per-tile: 8 rows x 16B hit all 32 banks (verified).
//   Pipeline: wait_group(1) -> sync -> compute(k) -> issue(k+2); the group
//   being waited on was issued 2 iterations earlier (no exposed tail).
// ---------------------------------------------------------------------------
#define BKB    32
#define ROWB   64                         // bytes per row (32 bf16)
#define PLB    (128 * ROWB)               // 8192 B per plane
#define STGB   (4 * PLB)                  // 32768 B per stage
#define NSTG   3
#define SMEM_MAIN (NSTG * STGB)           // 98304 bytes

__global__ __launch_bounds__(256)
void gemm_mainp(const float* __restrict__ bias, float* __restrict__ out) {
    extern __shared__ __align__(128) char sm[];
    const uint32_t sbase = (uint32_t)__cvta_generic_to_shared(sm);

    const int tid = threadIdx.x;
    const int m0  = blockIdx.y * BM;
    const int n0  = blockIdx.x * BN;
    const int wid = tid >> 5, lane = tid & 31;
    const int wm  = wid >> 2, wn = wid & 3;
    const int g   = lane >> 2, tig = lane & 3;

    float acc[4][4][4];
#pragma unroll
    for (int mt = 0; mt < 4; mt++)
#pragma unroll
        for (int nt = 0; nt < 4; nt++)
#pragma unroll
            for (int i = 0; i < 4; i++) acc[mt][nt][i] = 0.0f;

    const int lr = tid >> 2;           // 0..63 row (2 passes -> 128)
    const int c0 = tid & 3;            // 16B chunk index within 64B row

    const __nv_bfloat16* gXh = g_Xh + (size_t)m0 * KTOT;
    const __nv_bfloat16* gXl = g_Xl + (size_t)m0 * KTOT;
    const __nv_bfloat16* gBh = g_Bh + (size_t)n0 * KTOT;
    const __nv_bfloat16* gBl = g_Bl + (size_t)n0 * KTOT;

    // LDSM lane addressing (swizzled). p(r) = (r>>1)&3 invariant under +16/+64.
    const int l  = lane;
    const int rA = wm * 64 + (l & 7) + ((l >> 3) & 1) * 8;
    const int bA = (l >> 4) & 1;
    const uint32_t wA   = (uint32_t)((bA ^ ((rA >> 1) & 3)) * 16);
    const uint32_t aRow = (uint32_t)(rA * ROWB);
    const int rB = wn * 32 + (l & 7) + ((l >> 4) & 1) * 8;
    const int bB = (l >> 3) & 1;
    const uint32_t wB   = (uint32_t)((bB ^ ((rB >> 1) & 3)) * 16);
    const uint32_t bRow = (uint32_t)(rB * ROWB);

    auto issue = [&](int kt, int buf) {
        const int kb = kt * BKB;
        const uint32_t s = sbase + (uint32_t)(buf * STGB);
#pragma unroll
        for (int p = 0; p < 2; p++) {
            const int r = p * 64 + lr;
            const uint32_t so = s + (uint32_t)(r * ROWB + ((c0 ^ ((r >> 1) & 3)) * 16));
            const size_t go = (size_t)r * KTOT + kb + c0 * 8;
            cp_async16_s(so,           gXh + go);
            cp_async16_s(so + PLB,     gXl + go);
            cp_async16_s(so + 2 * PLB, gBh + go);
            cp_async16_s(so + 3 * PLB, gBl + go);
        }
        cp_commit();
    };

    issue(0, 0);
    issue(1, 1);

    const int NKT = KTOT / BKB;   // 132
    int buf = 0;
    for (int kt = 0; kt < NKT; kt++) {
        if (kt == NKT - 1) cp_wait0(); else cp_wait1();
        __syncthreads();

        const uint32_t stg = sbase + (uint32_t)(buf * STGB);
        const uint32_t aH  = stg + aRow;
        const uint32_t aL  = aH + PLB;
        const uint32_t bH  = stg + 2 * PLB + bRow;
        const uint32_t bL  = bH + PLB;

#pragma unroll
        for (int ks = 0; ks < 2; ks++) {
            const uint32_t ka = wA ^ (uint32_t)(ks << 5);
            const uint32_t kb_ = wB ^ (uint32_t)(ks << 5);
            uint32_t bh[4][2], bl[4][2];
            ldsm4(bh[0][0], bh[0][1], bh[1][0], bh[1][1], bH + kb_);
            ldsm4(bh[2][0], bh[2][1], bh[3][0], bh[3][1], bH + 1024 + kb_);
            ldsm4(bl[0][0], bl[0][1], bl[1][0], bl[1][1], bL + kb_);
            ldsm4(bl[2][0], bl[2][1], bl[3][0], bl[3][1], bL + 1024 + kb_);
#pragma unroll
            for (int mt = 0; mt < 4; mt++) {
                const uint32_t mtB = (uint32_t)(mt * 1024);
                uint32_t ah0, ah1, ah2, ah3, al0, al1, al2, al3;
                ldsm4(ah0, ah1, ah2, ah3, aH + mtB + ka);
                ldsm4(al0, al1, al2, al3, aL + mtB + ka);
#pragma unroll
                for (int nt = 0; nt < 4; nt++)
                    mma_bf16(acc[mt][nt], ah0, ah1, ah2, ah3, bh[nt][0], bh[nt][1]);
#pragma unroll
                for (int nt = 0; nt < 4; nt++)
                    mma_bf16(acc[mt][nt], al0, al1, al2, al3, bh[nt][0], bh[nt][1]);
#pragma unroll
                for (int nt = 0; nt < 4; nt++)
                    mma_bf16(acc[mt][nt], ah0, ah1, ah2, ah3, bl[nt][0], bl[nt][1]);
            }
        }

        __syncthreads();                  // all warps done with stage buf
        if (kt + 2 < NKT) issue(kt + 2, (buf + 2) % NSTG);
        buf = (buf + 1) % NSTG;
    }

    // Epilogue: add bias, write out
#pragma unroll
    for (int mt = 0; mt < 4; mt++) {
        const int row = m0 + wm * 64 + mt * 16 + g;
#pragma unroll
        for (int nt = 0; nt < 4; nt++) {
            const int col = n0 + wn * 32 + nt * 8 + 2 * tig;
            const float b0 = __ldg(&bias[col]);
            const float b1 = __ldg(&bias[col + 1]);
            float2 v0 = make_float2(acc[mt][nt][0] + b0, acc[mt][nt][1] + b1);
            float2 v1 = make_float2(acc[mt][nt][2] + b0, acc[mt][nt][3] + b1);
            *(float2*)&out[(size_t)row * D + col]       = v0;
            *(float2*)&out[(size_t)(row + 8) * D + col] = v1;
        }
    }
}

// ---------------------------------------------------------------------------
// Launch
// ---------------------------------------------------------------------------
extern "C" void kernel_launch(void* const* d_in, const int* in_sizes, int n_in,
                              void* d_out, int out_size) {
    const float* x     = (const float*)d_in[0];   // [4,2048,4096]
    const float* loraA = (const float*)d_in[1];   // [8,16,4096]
    const float* loraB = (const float*)d_in[2];   // [8,4096,16]
    const float* W     = (const float*)d_in[3];   // [4096,4096]
    const float* bias  = (const float*)d_in[4];   // [4096]
    const float* lw    = (const float*)d_in[5];   // [8]
    float* out = (float*)d_out;

    static bool attr_set = false;
    if (!attr_set) {
        cudaFuncSetAttribute(gemm_mainp, cudaFuncAttributeMaxDynamicSharedMemorySize,
                             SMEM_MAIN);
        attr_set = true;
    }

    gemm_h   <<<dim3(KS, MTOK / BM), 256>>>(x, loraA, lw);
    convert_x<<<(int)((size_t)MTOK * KTOT / 4 / 256), 256>>>(x);
    convert_b<<<(int)((size_t)D * KTOT / 4 / 256), 256>>>(W, loraB);
    gemm_mainp<<<dim3(D / BN, MTOK / BM), 256, SMEM_MAIN>>>(bias, out);
}